// round 10
// baseline (speedup 1.0000x reference)
#include <cuda_runtime.h>
#include <cuda_fp16.h>
#include <math.h>
#include <stdint.h>

#define B_    4
#define T_    2048
#define C_    1024
#define E_    8
#define H_    4096
#define NTOK  (B_ * T_)     // 8192
#define MAXBLK 80           // >= sum ceil(count_e/128) worst case (64+8)

// ---------------- scratch (device globals; no runtime allocation) -----------
__device__ int   g_idx[NTOK];
__device__ float g_prob[NTOK];
__device__ int   g_counts[E_];
__device__ int   g_offsets[E_ + 1];
__device__ int   g_cursor[E_];
__device__ int   g_perm[NTOK];
__device__ int   g_nblk;
__device__ int   g_blk_e[MAXBLK];
__device__ int   g_blk_r0[MAXBLK];

// fp16 operands (single-rounded; fp32 accumulate in MMA). Weights keep native
// layout: W1 [e][C][H], W2 [e][H][C]  (both are [k][n] for their GEMM).
__device__ __half g_xp[(size_t)NTOK * C_];        // permuted x  [p][C]
__device__ __half g_w1[(size_t)E_ * C_ * H_];     // fl16(W1)
__device__ __half g_w2[(size_t)E_ * H_ * C_];     // fl16(W2)
__device__ __half g_h[(size_t)NTOK * H_];         // hidden (permuted rows)

__device__ __forceinline__ float gelu_exact(float v) {
    return 0.5f * v * (1.0f + erff(v * 0.7071067811865476f));
}

__device__ __forceinline__ uint32_t smem_u32(const void* p) {
    uint32_t a;
    asm("{ .reg .u64 t; cvta.to.shared.u64 t, %1; cvt.u32.u64 %0, t; }"
        : "=r"(a) : "l"(p));
    return a;
}

#define LDSM4(R0, R1, R2, R3, addr)                                          \
    asm volatile("ldmatrix.sync.aligned.m8n8.x4.shared.b16 {%0,%1,%2,%3}, [%4];" \
                 : "=r"(R0), "=r"(R1), "=r"(R2), "=r"(R3) : "r"(addr))

#define LDSM4T(R0, R1, R2, R3, addr)                                         \
    asm volatile("ldmatrix.sync.aligned.m8n8.x4.trans.shared.b16 {%0,%1,%2,%3}, [%4];" \
                 : "=r"(R0), "=r"(R1), "=r"(R2), "=r"(R3) : "r"(addr))

#define MMA16816(C, A, B0, B1)                                               \
    asm volatile("mma.sync.aligned.m16n8k16.row.col.f32.f16.f16.f32 "        \
                 "{%0,%1,%2,%3},{%4,%5,%6,%7},{%8,%9},{%0,%1,%2,%3};"        \
                 : "+f"((C)[0]), "+f"((C)[1]), "+f"((C)[2]), "+f"((C)[3])    \
                 : "r"((A)[0]), "r"((A)[1]), "r"((A)[2]), "r"((A)[3]),       \
                   "r"(B0), "r"(B1))

#define CP_ASYNC16(dst, src)                                                 \
    asm volatile("cp.async.cg.shared.global [%0], [%1], 16;" :: "r"(dst), "l"(src))
#define CP_COMMIT()  asm volatile("cp.async.commit_group;" ::: "memory")
#define CP_WAIT2()   asm volatile("cp.async.wait_group 2;" ::: "memory")
#define CP_WAIT0()   asm volatile("cp.async.wait_group 0;" ::: "memory")

// ---------------- 0-3. routing -----------------------------------------------
__global__ void zero_counts_kernel() {
    if (threadIdx.x < E_) g_counts[threadIdx.x] = 0;
}

// one warp per token; float4 loads for x and Wr (L1-replay-friendly)
__global__ __launch_bounds__(256) void router_kernel(
        const float* __restrict__ x, const float* __restrict__ Wr,
        const float* __restrict__ br) {
    int warp = (blockIdx.x * blockDim.x + threadIdx.x) >> 5;
    int lane = threadIdx.x & 31;
    if (warp >= NTOK) return;
    const float* xr = x + (size_t)warp * C_;
    float acc[E_];
#pragma unroll
    for (int e = 0; e < E_; e++) acc[e] = 0.f;

#pragma unroll
    for (int i = 0; i < C_ / 128; i++) {
        int k = i * 128 + lane * 4;
        float4 xv = *(const float4*)(xr + k);
        const float4* wr = (const float4*)(Wr + (size_t)k * E_);
#pragma unroll
        for (int j = 0; j < 4; j++) {
            float xs = (j == 0) ? xv.x : (j == 1) ? xv.y : (j == 2) ? xv.z : xv.w;
            float4 w0 = wr[2 * j];
            float4 w1 = wr[2 * j + 1];
            acc[0] += xs * w0.x; acc[1] += xs * w0.y;
            acc[2] += xs * w0.z; acc[3] += xs * w0.w;
            acc[4] += xs * w1.x; acc[5] += xs * w1.y;
            acc[6] += xs * w1.z; acc[7] += xs * w1.w;
        }
    }
#pragma unroll
    for (int e = 0; e < E_; e++) {
#pragma unroll
        for (int off = 16; off > 0; off >>= 1)
            acc[e] += __shfl_xor_sync(0xffffffffu, acc[e], off);
    }
    if (lane == 0) {
        float lmax = -1e30f; int best = 0;
#pragma unroll
        for (int e = 0; e < E_; e++) {
            float l = acc[e] + br[e];
            acc[e] = l;
            if (l > lmax) { lmax = l; best = e; }
        }
        float s = 0.f;
#pragma unroll
        for (int e = 0; e < E_; e++) s += expf(acc[e] - lmax);
        g_prob[warp] = 1.0f / s;
        g_idx[warp]  = best;
        atomicAdd(&g_counts[best], 1);
    }
}

__global__ void offsets_kernel(float* aux_out) {
    int off = 0;
    float aux = 0.f;
    int nb = 0;
#pragma unroll
    for (int e = 0; e < E_; e++) {
        g_offsets[e] = off;
        g_cursor[e]  = off;
        int c = g_counts[e];
        for (int r0 = off; r0 < off + c; r0 += 128) {
            g_blk_e[nb]  = e;
            g_blk_r0[nb] = r0;
            nb++;
        }
        off += c;
        float frac = (float)c / (float)NTOK;
        float d = frac - (1.0f / (float)E_);
        aux += d * d;
    }
    g_offsets[E_] = off;
    g_nblk = nb;
    if (aux_out) *aux_out = aux / (float)E_;
}

__global__ void permute_kernel() {
    int t = blockIdx.x * blockDim.x + threadIdx.x;
    if (t >= NTOK) return;
    int e = g_idx[t];
    int pos = atomicAdd(&g_cursor[e], 1);
    g_perm[pos] = t;
}

// ---------------- 4. convert + permute x to fp16 ------------------------------
__global__ __launch_bounds__(256) void convert_x_kernel(const float* __restrict__ x) {
    int p = blockIdx.x;
    int tok = g_perm[p];
    int k = threadIdx.x * 4;
    float4 v = *(const float4*)(x + (size_t)tok * C_ + k);
    uint2 hw;
    hw.x = ((uint32_t)__half_as_ushort(__float2half_rn(v.y)) << 16)
           | __half_as_ushort(__float2half_rn(v.x));
    hw.y = ((uint32_t)__half_as_ushort(__float2half_rn(v.w)) << 16)
           | __half_as_ushort(__float2half_rn(v.z));
    *(uint2*)(g_xp + (size_t)p * C_ + k) = hw;
}

// ---------------- 5. weight convert fp32 -> fp16 (streaming, no transpose) ----
__global__ __launch_bounds__(256) void convert_w_kernel(
        const float4* __restrict__ src, __half* __restrict__ dst) {
    size_t i = (size_t)blockIdx.x * 256 + threadIdx.x;
    float4 v = src[i];
    uint2 hw;
    hw.x = ((uint32_t)__half_as_ushort(__float2half_rn(v.y)) << 16)
           | __half_as_ushort(__float2half_rn(v.x));
    hw.y = ((uint32_t)__half_as_ushort(__float2half_rn(v.w)) << 16)
           | __half_as_ushort(__float2half_rn(v.z));
    *(uint2*)(dst + i * 4) = hw;
}

// ---------------- 6/7. HMMA grouped GEMM (fp16, native-layout B) --------------
// A tile [128 m][32 k] pitch 80B (non-trans LDSM). B tile [32 k][128 n] pitch
// 272B (trans LDSM, conflict-free). 4-stage cp.async pipeline.
#define A_PITCH  80
#define A_TILE   10240            // 128*80
#define B_PITCH  272
#define B_TILE   8704             // 32*272
#define STAGE_B  (A_TILE + B_TILE)  // 18944
#define GEMM_SMEM (4 * STAGE_B)     // 75776

template<int MODE>
__global__ __launch_bounds__(256, 2) void gemm_hmma_kernel(
        const float* __restrict__ bias, float* __restrict__ out) {
    constexpr int KDIM = (MODE == 1) ? C_ : H_;
    constexpr int NTOT = (MODE == 1) ? H_ : C_;
    constexpr int NC   = KDIM / 32;        // chunks

    extern __shared__ char smem[];
    int bx = blockIdx.x;
    if (bx >= g_nblk) return;
    int e  = g_blk_e[bx];
    int r0 = g_blk_r0[bx];
    int row_end = g_offsets[e + 1];
    int n0 = blockIdx.y * 128;

    int tid  = threadIdx.x;
    int wid  = tid >> 5, lane = tid & 31;
    int wm   = wid & 3;          // warp row  (4 x 32 rows)
    int wn   = wid >> 2;         // warp col  (2 x 64 cols)

    const __half* A  = (MODE == 1) ? g_xp : g_h;
    const __half* Bw = ((MODE == 1) ? g_w1 : g_w2) + (size_t)e * KDIM * NTOT;

    uint32_t sbase = smem_u32(smem);

    // A copy mapping: rows tid>>2 and +64, k-seg tid&3 (16B each)
    int rowA0 = tid >> 2,  kc = tid & 3;
    int rowA1 = rowA0 + 64;
    int pA0 = r0 + rowA0; if (pA0 >= row_end) pA0 = r0;
    int pA1 = r0 + rowA1; if (pA1 >= row_end) pA1 = r0;
    uint32_t offA0 = rowA0 * A_PITCH + kc * 16;
    uint32_t offA1 = rowA1 * A_PITCH + kc * 16;
    // B copy mapping: k-row tid>>3 (0..31), n-seg tid&7 and +8 (16B each)
    int brow = tid >> 3, bseg = tid & 7;
    uint32_t offB0 = brow * B_PITCH + bseg * 16;
    uint32_t offB1 = offB0 + 128;

    float acc[2][8][4];
#pragma unroll
    for (int i = 0; i < 2; i++)
#pragma unroll
        for (int j = 0; j < 8; j++)
#pragma unroll
            for (int q = 0; q < 4; q++) acc[i][j][q] = 0.f;

    auto issue = [&](int chunk, int slot) {
        int k0 = chunk * 32;
        uint32_t sA = sbase + slot * STAGE_B;
        uint32_t sB = sA + A_TILE;
        CP_ASYNC16(sA + offA0, A + (size_t)pA0 * KDIM + k0 + kc * 8);
        CP_ASYNC16(sA + offA1, A + (size_t)pA1 * KDIM + k0 + kc * 8);
        const __half* bsrc = Bw + (size_t)(k0 + brow) * NTOT + n0 + bseg * 8;
        CP_ASYNC16(sB + offB0, bsrc);
        CP_ASYNC16(sB + offB1, bsrc + 64);
    };

    issue(0, 0); CP_COMMIT();
    issue(1, 1); CP_COMMIT();
    issue(2, 2); CP_COMMIT();

    // lane address pieces
    int lrow = ((lane >> 3) & 1) * 8 + (lane & 7);        // A: m-row within 16
    int lkof = ((lane >> 4) & 1) * 8;                     // A: k-offset
    int bkrow = (lane & 7) + ((lane >> 4) & 1) * 8;       // B: k-row within 16
    int bncol = ((lane >> 3) & 1) * 8;                    // B: n-offset within 16

    for (int c = 0; c < NC; c++) {
        int slot = c & 3;
        if (c + 3 < NC) { CP_WAIT2(); }
        else            { CP_WAIT0(); }
        __syncthreads();
        if (c + 3 < NC) {
            issue(c + 3, (c + 3) & 3); CP_COMMIT();
        }

        uint32_t sA = sbase + slot * STAGE_B;
        uint32_t sB = sA + A_TILE;

#pragma unroll
        for (int kk = 0; kk < 2; kk++) {
            int k0 = kk * 16;
            // B fragments via trans ldmatrix on [k][n] tile:
            // reg0=(k0-7,n0-7) reg1=(k0-7,n8-15) reg2=(k8-15,n0-7) reg3=(k8-15,n8-15)
            uint32_t b[4][4];
#pragma unroll
            for (int g = 0; g < 4; g++) {
                uint32_t addr = sB + (uint32_t)((k0 + bkrow) * B_PITCH
                                                + (wn * 64 + g * 16 + bncol) * 2);
                LDSM4T(b[g][0], b[g][1], b[g][2], b[g][3], addr);
            }
            uint32_t a[2][4];
#pragma unroll
            for (int mi = 0; mi < 2; mi++) {
                uint32_t addr = sA + (uint32_t)((wm * 32 + mi * 16 + lrow) * A_PITCH
                                                + (k0 + lkof) * 2);
                LDSM4(a[mi][0], a[mi][1], a[mi][2], a[mi][3], addr);
            }
#pragma unroll
            for (int mi = 0; mi < 2; mi++)
#pragma unroll
                for (int ni = 0; ni < 8; ni++) {
                    int gg = ni >> 1, hh = ni & 1;
                    MMA16816(acc[mi][ni], a[mi], b[gg][hh], b[gg][hh + 2]);
                }
        }
    }

    // ---------------- epilogue ----------------
    int colbase = n0 + wn * 64 + (lane & 3) * 2;
    int rbase   = r0 + wm * 32 + (lane >> 2);
    size_t bofs = (size_t)e * NTOT;

#pragma unroll
    for (int mi = 0; mi < 2; mi++) {
#pragma unroll
        for (int half = 0; half < 2; half++) {
            int p = rbase + mi * 16 + half * 8;
            if (p >= row_end) continue;
            if (MODE == 1) {
#pragma unroll
                for (int ni = 0; ni < 8; ni++) {
                    int col = colbase + ni * 8;
                    float v0 = acc[mi][ni][half * 2]     + bias[bofs + col];
                    float v1 = acc[mi][ni][half * 2 + 1] + bias[bofs + col + 1];
                    v0 = gelu_exact(v0);
                    v1 = gelu_exact(v1);
                    uint32_t hw = ((uint32_t)__half_as_ushort(__float2half_rn(v1)) << 16)
                                  | __half_as_ushort(__float2half_rn(v0));
                    *(uint32_t*)(g_h + (size_t)p * H_ + col) = hw;
                }
            } else {
                int tok = g_perm[p];
                float gprob = g_prob[tok];
                float* orow = out + (size_t)tok * C_;
#pragma unroll
                for (int ni = 0; ni < 8; ni++) {
                    int col = colbase + ni * 8;
                    float2 o;
                    o.x = gprob * (acc[mi][ni][half * 2]     + bias[bofs + col]);
                    o.y = gprob * (acc[mi][ni][half * 2 + 1] + bias[bofs + col + 1]);
                    *(float2*)(orow + col) = o;
                }
            }
        }
    }
}

// ---------------- launch ------------------------------------------------------
extern "C" void kernel_launch(void* const* d_in, const int* in_sizes, int n_in,
                              void* d_out, int out_size) {
    const float* x  = (const float*)d_in[0];
    const float* Wr = (const float*)d_in[1];
    const float* br = (const float*)d_in[2];
    const float* W1 = (const float*)d_in[3];
    const float* b1 = (const float*)d_in[4];
    const float* W2 = (const float*)d_in[5];
    const float* b2 = (const float*)d_in[6];
    float* out = (float*)d_out;

    float* aux_ptr = (out_size > NTOK * C_) ? (out + (out_size - 1)) : nullptr;

    cudaFuncSetAttribute(gemm_hmma_kernel<1>,
                         cudaFuncAttributeMaxDynamicSharedMemorySize, GEMM_SMEM);
    cudaFuncSetAttribute(gemm_hmma_kernel<2>,
                         cudaFuncAttributeMaxDynamicSharedMemorySize, GEMM_SMEM);

    __half* d_w1h; cudaGetSymbolAddress((void**)&d_w1h, g_w1);
    __half* d_w2h; cudaGetSymbolAddress((void**)&d_w2h, g_w2);
    convert_w_kernel<<<(E_ * C_ * H_) / 4 / 256, 256>>>((const float4*)W1, d_w1h);
    convert_w_kernel<<<(E_ * H_ * C_) / 4 / 256, 256>>>((const float4*)W2, d_w2h);

    zero_counts_kernel<<<1, 32>>>();
    router_kernel<<<NTOK / 8, 256>>>(x, Wr, br);
    offsets_kernel<<<1, 1>>>(aux_ptr);
    permute_kernel<<<NTOK / 256, 256>>>();
    convert_x_kernel<<<NTOK, 256>>>(x);

    gemm_hmma_kernel<1><<<dim3(72, H_ / 128), 256, GEMM_SMEM>>>(b1, nullptr);
    gemm_hmma_kernel<2><<<dim3(72, C_ / 128), 256, GEMM_SMEM>>>(b2, out);
}

// round 11
// speedup vs baseline: 1.0801x; 1.0801x over previous
#include <cuda_runtime.h>
#include <cuda_fp16.h>
#include <math.h>
#include <stdint.h>

#define B_    4
#define T_    2048
#define C_    1024
#define E_    8
#define H_    4096
#define NTOK  (B_ * T_)     // 8192
#define MAXBLK 80           // >= sum ceil(count_e/128) worst case (64+8)

// ---------------- scratch (device globals; no runtime allocation) -----------
__device__ int   g_idx[NTOK];
__device__ float g_prob[NTOK];
__device__ int   g_counts[E_];
__device__ int   g_offsets[E_ + 1];
__device__ int   g_cursor[E_];
__device__ int   g_perm[NTOK];
__device__ int   g_nblk;
__device__ int   g_blk_e[MAXBLK];
__device__ int   g_blk_r0[MAXBLK];

// fp16 operands (single-rounded; fp32 accumulate in MMA). Weights keep native
// layout: W1 [e][C][H], W2 [e][H][C]  (both are [k][n] for their GEMM).
__device__ __half g_xp[(size_t)NTOK * C_];        // permuted x  [p][C]
__device__ __half g_w1[(size_t)E_ * C_ * H_];     // fl16(W1)
__device__ __half g_w2[(size_t)E_ * H_ * C_];     // fl16(W2)
__device__ __half g_h[(size_t)NTOK * H_];         // hidden (permuted rows)

__device__ __forceinline__ float gelu_exact(float v) {
    return 0.5f * v * (1.0f + erff(v * 0.7071067811865476f));
}

__device__ __forceinline__ uint32_t smem_u32(const void* p) {
    uint32_t a;
    asm("{ .reg .u64 t; cvta.to.shared.u64 t, %1; cvt.u32.u64 %0, t; }"
        : "=r"(a) : "l"(p));
    return a;
}

#define LDSM4(R0, R1, R2, R3, addr)                                          \
    asm volatile("ldmatrix.sync.aligned.m8n8.x4.shared.b16 {%0,%1,%2,%3}, [%4];" \
                 : "=r"(R0), "=r"(R1), "=r"(R2), "=r"(R3) : "r"(addr))

#define LDSM4T(R0, R1, R2, R3, addr)                                         \
    asm volatile("ldmatrix.sync.aligned.m8n8.x4.trans.shared.b16 {%0,%1,%2,%3}, [%4];" \
                 : "=r"(R0), "=r"(R1), "=r"(R2), "=r"(R3) : "r"(addr))

#define MMA16816(C, A, B0, B1)                                               \
    asm volatile("mma.sync.aligned.m16n8k16.row.col.f32.f16.f16.f32 "        \
                 "{%0,%1,%2,%3},{%4,%5,%6,%7},{%8,%9},{%0,%1,%2,%3};"        \
                 : "+f"((C)[0]), "+f"((C)[1]), "+f"((C)[2]), "+f"((C)[3])    \
                 : "r"((A)[0]), "r"((A)[1]), "r"((A)[2]), "r"((A)[3]),       \
                   "r"(B0), "r"(B1))

#define CP_ASYNC16(dst, src)                                                 \
    asm volatile("cp.async.cg.shared.global [%0], [%1], 16;" :: "r"(dst), "l"(src))
#define CP_COMMIT()  asm volatile("cp.async.commit_group;" ::: "memory")
#define CP_WAIT2()   asm volatile("cp.async.wait_group 2;" ::: "memory")
#define CP_WAIT0()   asm volatile("cp.async.wait_group 0;" ::: "memory")

// ---------------- 0-3. routing -----------------------------------------------
__global__ void zero_counts_kernel() {
    if (threadIdx.x < E_) g_counts[threadIdx.x] = 0;
}

// one warp per token; Wr staged transposed in smem -> conflict-free LDS.128,
// x read as dense coalesced float4 (no L1 replays)
__global__ __launch_bounds__(256) void router_kernel(
        const float* __restrict__ x, const float* __restrict__ Wr,
        const float* __restrict__ br) {
    __shared__ float WrT[E_ * C_];          // 32 KB, [e][k]
    int tid = threadIdx.x;
    // coalesced gmem read; transposed smem store (one-time)
    for (int idx = tid; idx < E_ * C_; idx += 256) {
        int k = idx >> 3, e = idx & 7;
        WrT[e * C_ + k] = Wr[idx];
    }
    __syncthreads();

    int warp = (blockIdx.x * blockDim.x + tid) >> 5;
    int lane = tid & 31;
    const float* xr = x + (size_t)warp * C_;

    float acc[E_];
#pragma unroll
    for (int e = 0; e < E_; e++) acc[e] = 0.f;

#pragma unroll
    for (int i = 0; i < C_ / 128; i++) {
        int k = i * 128 + lane * 4;
        float4 xv = *(const float4*)(xr + k);
#pragma unroll
        for (int e = 0; e < E_; e++) {
            float4 w = *(const float4*)(WrT + e * C_ + k);
            acc[e] += xv.x * w.x + xv.y * w.y + xv.z * w.z + xv.w * w.w;
        }
    }
#pragma unroll
    for (int e = 0; e < E_; e++) {
#pragma unroll
        for (int off = 16; off > 0; off >>= 1)
            acc[e] += __shfl_xor_sync(0xffffffffu, acc[e], off);
    }
    if (lane == 0) {
        float lmax = -1e30f; int best = 0;
#pragma unroll
        for (int e = 0; e < E_; e++) {
            float l = acc[e] + br[e];
            acc[e] = l;
            if (l > lmax) { lmax = l; best = e; }
        }
        float s = 0.f;
#pragma unroll
        for (int e = 0; e < E_; e++) s += expf(acc[e] - lmax);
        g_prob[warp] = 1.0f / s;
        g_idx[warp]  = best;
        atomicAdd(&g_counts[best], 1);
    }
}

__global__ void offsets_kernel(float* aux_out) {
    int off = 0;
    float aux = 0.f;
    int nb = 0;
#pragma unroll
    for (int e = 0; e < E_; e++) {
        g_offsets[e] = off;
        g_cursor[e]  = off;
        int c = g_counts[e];
        for (int r0 = off; r0 < off + c; r0 += 128) {
            g_blk_e[nb]  = e;
            g_blk_r0[nb] = r0;
            nb++;
        }
        off += c;
        float frac = (float)c / (float)NTOK;
        float d = frac - (1.0f / (float)E_);
        aux += d * d;
    }
    g_offsets[E_] = off;
    g_nblk = nb;
    if (aux_out) *aux_out = aux / (float)E_;
}

__global__ void permute_kernel() {
    int t = blockIdx.x * blockDim.x + threadIdx.x;
    if (t >= NTOK) return;
    int e = g_idx[t];
    int pos = atomicAdd(&g_cursor[e], 1);
    g_perm[pos] = t;
}

// ---------------- 4. convert + permute x to fp16 ------------------------------
__global__ __launch_bounds__(256) void convert_x_kernel(const float* __restrict__ x) {
    int p = blockIdx.x;
    int tok = g_perm[p];
    int k = threadIdx.x * 4;
    float4 v = *(const float4*)(x + (size_t)tok * C_ + k);
    uint2 hw;
    hw.x = ((uint32_t)__half_as_ushort(__float2half_rn(v.y)) << 16)
           | __half_as_ushort(__float2half_rn(v.x));
    hw.y = ((uint32_t)__half_as_ushort(__float2half_rn(v.w)) << 16)
           | __half_as_ushort(__float2half_rn(v.z));
    *(uint2*)(g_xp + (size_t)p * C_ + k) = hw;
}

// ---------------- 5. weight convert fp32 -> fp16 (8 floats/thread) -----------
__global__ __launch_bounds__(256) void convert_w_kernel(
        const float4* __restrict__ src, __half* __restrict__ dst) {
    size_t i = ((size_t)blockIdx.x * 256 + threadIdx.x) * 2;
    float4 v0 = src[i];
    float4 v1 = src[i + 1];
    uint4 hw;
    hw.x = ((uint32_t)__half_as_ushort(__float2half_rn(v0.y)) << 16)
           | __half_as_ushort(__float2half_rn(v0.x));
    hw.y = ((uint32_t)__half_as_ushort(__float2half_rn(v0.w)) << 16)
           | __half_as_ushort(__float2half_rn(v0.z));
    hw.z = ((uint32_t)__half_as_ushort(__float2half_rn(v1.y)) << 16)
           | __half_as_ushort(__float2half_rn(v1.x));
    hw.w = ((uint32_t)__half_as_ushort(__float2half_rn(v1.w)) << 16)
           | __half_as_ushort(__float2half_rn(v1.z));
    *(uint4*)(dst + i * 4) = hw;
}

// ---------------- 6/7. HMMA grouped GEMM (fp16, native-layout B) --------------
// A tile [128 m][32 k] pitch 80B (non-trans LDSM). B tile [32 k][128 n] pitch
// 272B (trans LDSM, conflict-free). 4-stage cp.async pipeline.
#define A_PITCH  80
#define A_TILE   10240            // 128*80
#define B_PITCH  272
#define B_TILE   8704             // 32*272
#define STAGE_B  (A_TILE + B_TILE)  // 18944
#define GEMM_SMEM (4 * STAGE_B)     // 75776

template<int MODE>
__global__ __launch_bounds__(256, 2) void gemm_hmma_kernel(
        const float* __restrict__ bias, float* __restrict__ out) {
    constexpr int KDIM = (MODE == 1) ? C_ : H_;
    constexpr int NTOT = (MODE == 1) ? H_ : C_;
    constexpr int NC   = KDIM / 32;        // chunks

    extern __shared__ char smem[];
    int bx = blockIdx.x;
    if (bx >= g_nblk) return;
    int e  = g_blk_e[bx];
    int r0 = g_blk_r0[bx];
    int row_end = g_offsets[e + 1];
    int n0 = blockIdx.y * 128;

    int tid  = threadIdx.x;
    int wid  = tid >> 5, lane = tid & 31;
    int wm   = wid & 3;          // warp row  (4 x 32 rows)
    int wn   = wid >> 2;         // warp col  (2 x 64 cols)

    const __half* A  = (MODE == 1) ? g_xp : g_h;
    const __half* Bw = ((MODE == 1) ? g_w1 : g_w2) + (size_t)e * KDIM * NTOT;

    uint32_t sbase = smem_u32(smem);

    // A copy mapping: rows tid>>2 and +64, k-seg tid&3 (16B each)
    int rowA0 = tid >> 2,  kc = tid & 3;
    int rowA1 = rowA0 + 64;
    int pA0 = r0 + rowA0; if (pA0 >= row_end) pA0 = r0;
    int pA1 = r0 + rowA1; if (pA1 >= row_end) pA1 = r0;
    uint32_t offA0 = rowA0 * A_PITCH + kc * 16;
    uint32_t offA1 = rowA1 * A_PITCH + kc * 16;
    // B copy mapping: k-row tid>>3 (0..31), n-seg tid&7 and +8 (16B each)
    int brow = tid >> 3, bseg = tid & 7;
    uint32_t offB0 = brow * B_PITCH + bseg * 16;
    uint32_t offB1 = offB0 + 128;

    float acc[2][8][4];
#pragma unroll
    for (int i = 0; i < 2; i++)
#pragma unroll
        for (int j = 0; j < 8; j++)
#pragma unroll
            for (int q = 0; q < 4; q++) acc[i][j][q] = 0.f;

    auto issue = [&](int chunk, int slot) {
        int k0 = chunk * 32;
        uint32_t sA = sbase + slot * STAGE_B;
        uint32_t sB = sA + A_TILE;
        CP_ASYNC16(sA + offA0, A + (size_t)pA0 * KDIM + k0 + kc * 8);
        CP_ASYNC16(sA + offA1, A + (size_t)pA1 * KDIM + k0 + kc * 8);
        const __half* bsrc = Bw + (size_t)(k0 + brow) * NTOT + n0 + bseg * 8;
        CP_ASYNC16(sB + offB0, bsrc);
        CP_ASYNC16(sB + offB1, bsrc + 64);
    };

    issue(0, 0); CP_COMMIT();
    issue(1, 1); CP_COMMIT();
    issue(2, 2); CP_COMMIT();

    // lane address pieces
    int lrow = ((lane >> 3) & 1) * 8 + (lane & 7);        // A: m-row within 16
    int lkof = ((lane >> 4) & 1) * 8;                     // A: k-offset
    int bkrow = (lane & 7) + ((lane >> 4) & 1) * 8;       // B: k-row within 16
    int bncol = ((lane >> 3) & 1) * 8;                    // B: n-offset within 16

    for (int c = 0; c < NC; c++) {
        int slot = c & 3;
        if (c + 3 < NC) { CP_WAIT2(); }
        else            { CP_WAIT0(); }
        __syncthreads();
        if (c + 3 < NC) {
            issue(c + 3, (c + 3) & 3); CP_COMMIT();
        }

        uint32_t sA = sbase + slot * STAGE_B;
        uint32_t sB = sA + A_TILE;

#pragma unroll
        for (int kk = 0; kk < 2; kk++) {
            int k0 = kk * 16;
            // B fragments via trans ldmatrix on [k][n] tile:
            // reg0=(k0-7,n0-7) reg1=(k0-7,n8-15) reg2=(k8-15,n0-7) reg3=(k8-15,n8-15)
            uint32_t b[4][4];
#pragma unroll
            for (int g = 0; g < 4; g++) {
                uint32_t addr = sB + (uint32_t)((k0 + bkrow) * B_PITCH
                                                + (wn * 64 + g * 16 + bncol) * 2);
                LDSM4T(b[g][0], b[g][1], b[g][2], b[g][3], addr);
            }
            uint32_t a[2][4];
#pragma unroll
            for (int mi = 0; mi < 2; mi++) {
                uint32_t addr = sA + (uint32_t)((wm * 32 + mi * 16 + lrow) * A_PITCH
                                                + (k0 + lkof) * 2);
                LDSM4(a[mi][0], a[mi][1], a[mi][2], a[mi][3], addr);
            }
#pragma unroll
            for (int mi = 0; mi < 2; mi++)
#pragma unroll
                for (int ni = 0; ni < 8; ni++) {
                    int gg = ni >> 1, hh = ni & 1;
                    MMA16816(acc[mi][ni], a[mi], b[gg][hh], b[gg][hh + 2]);
                }
        }
    }

    // ---------------- epilogue ----------------
    int colbase = n0 + wn * 64 + (lane & 3) * 2;
    int rbase   = r0 + wm * 32 + (lane >> 2);
    size_t bofs = (size_t)e * NTOT;

#pragma unroll
    for (int mi = 0; mi < 2; mi++) {
#pragma unroll
        for (int half = 0; half < 2; half++) {
            int p = rbase + mi * 16 + half * 8;
            if (p >= row_end) continue;
            if (MODE == 1) {
#pragma unroll
                for (int ni = 0; ni < 8; ni++) {
                    int col = colbase + ni * 8;
                    float v0 = acc[mi][ni][half * 2]     + bias[bofs + col];
                    float v1 = acc[mi][ni][half * 2 + 1] + bias[bofs + col + 1];
                    v0 = gelu_exact(v0);
                    v1 = gelu_exact(v1);
                    uint32_t hw = ((uint32_t)__half_as_ushort(__float2half_rn(v1)) << 16)
                                  | __half_as_ushort(__float2half_rn(v0));
                    *(uint32_t*)(g_h + (size_t)p * H_ + col) = hw;
                }
            } else {
                int tok = g_perm[p];
                float gprob = g_prob[tok];
                float* orow = out + (size_t)tok * C_;
#pragma unroll
                for (int ni = 0; ni < 8; ni++) {
                    int col = colbase + ni * 8;
                    float2 o;
                    o.x = gprob * (acc[mi][ni][half * 2]     + bias[bofs + col]);
                    o.y = gprob * (acc[mi][ni][half * 2 + 1] + bias[bofs + col + 1]);
                    *(float2*)(orow + col) = o;
                }
            }
        }
    }
}

// ---------------- launch ------------------------------------------------------
extern "C" void kernel_launch(void* const* d_in, const int* in_sizes, int n_in,
                              void* d_out, int out_size) {
    const float* x  = (const float*)d_in[0];
    const float* Wr = (const float*)d_in[1];
    const float* br = (const float*)d_in[2];
    const float* W1 = (const float*)d_in[3];
    const float* b1 = (const float*)d_in[4];
    const float* W2 = (const float*)d_in[5];
    const float* b2 = (const float*)d_in[6];
    float* out = (float*)d_out;

    float* aux_ptr = (out_size > NTOK * C_) ? (out + (out_size - 1)) : nullptr;

    cudaFuncSetAttribute(gemm_hmma_kernel<1>,
                         cudaFuncAttributeMaxDynamicSharedMemorySize, GEMM_SMEM);
    cudaFuncSetAttribute(gemm_hmma_kernel<2>,
                         cudaFuncAttributeMaxDynamicSharedMemorySize, GEMM_SMEM);

    __half* d_w1h; cudaGetSymbolAddress((void**)&d_w1h, g_w1);
    __half* d_w2h; cudaGetSymbolAddress((void**)&d_w2h, g_w2);
    convert_w_kernel<<<(E_ * C_ * H_) / 8 / 256, 256>>>((const float4*)W1, d_w1h);
    convert_w_kernel<<<(E_ * H_ * C_) / 8 / 256, 256>>>((const float4*)W2, d_w2h);

    zero_counts_kernel<<<1, 32>>>();
    router_kernel<<<NTOK / 8, 256>>>(x, Wr, br);
    offsets_kernel<<<1, 1>>>(aux_ptr);
    permute_kernel<<<NTOK / 256, 256>>>();
    convert_x_kernel<<<NTOK, 256>>>(x);

    gemm_hmma_kernel<1><<<dim3(72, H_ / 128), 256, GEMM_SMEM>>>(b1, nullptr);
    gemm_hmma_kernel<2><<<dim3(72, C_ / 128), 256, GEMM_SMEM>>>(b2, out);
}

// round 13
// speedup vs baseline: 1.1029x; 1.0211x over previous
#include <cuda_runtime.h>
#include <cuda_fp16.h>
#include <math.h>
#include <stdint.h>

#define B_    4
#define T_    2048
#define C_    1024
#define E_    8
#define H_    4096
#define NTOK  (B_ * T_)     // 8192
#define MAXBLK 80           // >= sum ceil(count_e/128) worst case (64+8)

// ---------------- scratch (device globals; no runtime allocation) -----------
__device__ int   g_idx[NTOK];
__device__ float g_prob[NTOK];
__device__ int   g_counts[E_];
__device__ int   g_offsets[E_ + 1];
__device__ int   g_cursor[E_];
__device__ int   g_perm[NTOK];
__device__ int   g_nblk;
__device__ int   g_blk_e[MAXBLK];
__device__ int   g_blk_r0[MAXBLK];

// fp16 operands (single-rounded; fp32 accumulate in MMA). Weights keep native
// layout: W1 [e][C][H], W2 [e][H][C]  (both are [k][n] for their GEMM).
__device__ __half g_x16[(size_t)NTOK * C_];       // fp16 x, UNpermuted (router)
__device__ __half g_w1[(size_t)E_ * C_ * H_];     // fl16(W1)
__device__ __half g_w2[(size_t)E_ * H_ * C_];     // fl16(W2)
__device__ __half g_h[(size_t)NTOK * H_];         // hidden (permuted rows)

__device__ __forceinline__ float gelu_exact(float v) {
    return 0.5f * v * (1.0f + erff(v * 0.7071067811865476f));
}

__device__ __forceinline__ uint32_t smem_u32(const void* p) {
    uint32_t a;
    asm("{ .reg .u64 t; cvta.to.shared.u64 t, %1; cvt.u32.u64 %0, t; }"
        : "=r"(a) : "l"(p));
    return a;
}

#define LDSM4(R0, R1, R2, R3, addr)                                          \
    asm volatile("ldmatrix.sync.aligned.m8n8.x4.shared.b16 {%0,%1,%2,%3}, [%4];" \
                 : "=r"(R0), "=r"(R1), "=r"(R2), "=r"(R3) : "r"(addr))

#define LDSM4T(R0, R1, R2, R3, addr)                                         \
    asm volatile("ldmatrix.sync.aligned.m8n8.x4.trans.shared.b16 {%0,%1,%2,%3}, [%4];" \
                 : "=r"(R0), "=r"(R1), "=r"(R2), "=r"(R3) : "r"(addr))

#define MMA16816(C, A, B0, B1)                                               \
    asm volatile("mma.sync.aligned.m16n8k16.row.col.f32.f16.f16.f32 "        \
                 "{%0,%1,%2,%3},{%4,%5,%6,%7},{%8,%9},{%0,%1,%2,%3};"        \
                 : "+f"((C)[0]), "+f"((C)[1]), "+f"((C)[2]), "+f"((C)[3])    \
                 : "r"((A)[0]), "r"((A)[1]), "r"((A)[2]), "r"((A)[3]),       \
                   "r"(B0), "r"(B1))

#define CP_ASYNC16(dst, src)                                                 \
    asm volatile("cp.async.cg.shared.global [%0], [%1], 16;" :: "r"(dst), "l"(src))
#define CP_COMMIT()  asm volatile("cp.async.commit_group;" ::: "memory")
#define CP_WAIT2()   asm volatile("cp.async.wait_group 2;" ::: "memory")
#define CP_WAIT0()   asm volatile("cp.async.wait_group 0;" ::: "memory")

// ---------------- 0-3. routing -----------------------------------------------
__global__ void zero_counts_kernel() {
    if (threadIdx.x < E_) g_counts[threadIdx.x] = 0;
}

// 4 tokens per warp (Wr smem values reused x4); also emits fp16 x (unpermuted).
__global__ __launch_bounds__(256) void router_kernel(
        const float* __restrict__ x, const float* __restrict__ Wr,
        const float* __restrict__ br) {
    __shared__ float WrT[E_ * C_];          // 32 KB, [e][k]
    int tid = threadIdx.x;
    for (int idx = tid; idx < E_ * C_; idx += 256) {
        int k = idx >> 3, e = idx & 7;
        WrT[e * C_ + k] = Wr[idx];
    }
    __syncthreads();

    int lane = tid & 31;
    int t0 = (blockIdx.x * 8 + (tid >> 5)) * 4;     // 4 consecutive tokens/warp

    float acc[4][E_];
#pragma unroll
    for (int j = 0; j < 4; j++)
#pragma unroll
        for (int e = 0; e < E_; e++) acc[j][e] = 0.f;

#pragma unroll
    for (int i = 0; i < C_ / 128; i++) {
        int k = i * 128 + lane * 4;
        float4 xv[4];
#pragma unroll
        for (int j = 0; j < 4; j++) {
            xv[j] = *(const float4*)(x + (size_t)(t0 + j) * C_ + k);
            // fp16 conversion fused here (same rounding as old convert_x)
            uint2 hw;
            hw.x = ((uint32_t)__half_as_ushort(__float2half_rn(xv[j].y)) << 16)
                   | __half_as_ushort(__float2half_rn(xv[j].x));
            hw.y = ((uint32_t)__half_as_ushort(__float2half_rn(xv[j].w)) << 16)
                   | __half_as_ushort(__float2half_rn(xv[j].z));
            *(uint2*)(g_x16 + (size_t)(t0 + j) * C_ + k) = hw;
        }
#pragma unroll
        for (int e = 0; e < E_; e++) {
            float4 w = *(const float4*)(WrT + e * C_ + k);
#pragma unroll
            for (int j = 0; j < 4; j++)
                acc[j][e] += xv[j].x * w.x + xv[j].y * w.y
                           + xv[j].z * w.z + xv[j].w * w.w;
        }
    }
#pragma unroll
    for (int j = 0; j < 4; j++) {
#pragma unroll
        for (int e = 0; e < E_; e++) {
#pragma unroll
            for (int off = 16; off > 0; off >>= 1)
                acc[j][e] += __shfl_xor_sync(0xffffffffu, acc[j][e], off);
        }
        if (lane == 0) {
            float lmax = -1e30f; int best = 0;
#pragma unroll
            for (int e = 0; e < E_; e++) {
                float l = acc[j][e] + br[e];
                acc[j][e] = l;
                if (l > lmax) { lmax = l; best = e; }
            }
            float s = 0.f;
#pragma unroll
            for (int e = 0; e < E_; e++) s += expf(acc[j][e] - lmax);
            g_prob[t0 + j] = 1.0f / s;
            g_idx[t0 + j]  = best;
            atomicAdd(&g_counts[best], 1);
        }
    }
}

__global__ void offsets_kernel(float* aux_out) {
    int off = 0;
    float aux = 0.f;
    int nb = 0;
#pragma unroll
    for (int e = 0; e < E_; e++) {
        g_offsets[e] = off;
        g_cursor[e]  = off;
        int c = g_counts[e];
        for (int r0 = off; r0 < off + c; r0 += 128) {
            g_blk_e[nb]  = e;
            g_blk_r0[nb] = r0;
            nb++;
        }
        off += c;
        float frac = (float)c / (float)NTOK;
        float d = frac - (1.0f / (float)E_);
        aux += d * d;
    }
    g_offsets[E_] = off;
    g_nblk = nb;
    if (aux_out) *aux_out = aux / (float)E_;
}

__global__ void permute_kernel() {
    int t = blockIdx.x * blockDim.x + threadIdx.x;
    if (t >= NTOK) return;
    int e = g_idx[t];
    int pos = atomicAdd(&g_cursor[e], 1);
    g_perm[pos] = t;
}

// ---------------- 5. weight convert fp32 -> fp16 (8 floats/thread) -----------
__global__ __launch_bounds__(256) void convert_w_kernel(
        const float4* __restrict__ src, __half* __restrict__ dst) {
    size_t i = ((size_t)blockIdx.x * 256 + threadIdx.x) * 2;
    float4 v0 = src[i];
    float4 v1 = src[i + 1];
    uint4 hw;
    hw.x = ((uint32_t)__half_as_ushort(__float2half_rn(v0.y)) << 16)
           | __half_as_ushort(__float2half_rn(v0.x));
    hw.y = ((uint32_t)__half_as_ushort(__float2half_rn(v0.w)) << 16)
           | __half_as_ushort(__float2half_rn(v0.z));
    hw.z = ((uint32_t)__half_as_ushort(__float2half_rn(v1.y)) << 16)
           | __half_as_ushort(__float2half_rn(v1.x));
    hw.w = ((uint32_t)__half_as_ushort(__float2half_rn(v1.w)) << 16)
           | __half_as_ushort(__float2half_rn(v1.z));
    *(uint4*)(dst + i * 4) = hw;
}

// ---------------- 6/7. HMMA grouped GEMM (fp16, native-layout B) --------------
// A tile [128 m][32 k] pitch 80B (non-trans LDSM). B tile [32 k][128 n] pitch
// 272B (trans LDSM, conflict-free). 4-stage cp.async pipeline.
// MODE 1 gathers A rows from unpermuted g_x16 via g_perm.
#define A_PITCH  80
#define A_TILE   10240            // 128*80
#define B_PITCH  272
#define B_TILE   8704             // 32*272
#define STAGE_B  (A_TILE + B_TILE)  // 18944
#define GEMM_SMEM (4 * STAGE_B)     // 75776

template<int MODE>
__global__ __launch_bounds__(256, 2) void gemm_hmma_kernel(
        const float* __restrict__ bias, float* __restrict__ out) {
    constexpr int KDIM = (MODE == 1) ? C_ : H_;
    constexpr int NTOT = (MODE == 1) ? H_ : C_;
    constexpr int NC   = KDIM / 32;        // chunks

    extern __shared__ char smem[];
    int bx = blockIdx.x;
    if (bx >= g_nblk) return;
    int e  = g_blk_e[bx];
    int r0 = g_blk_r0[bx];
    int row_end = g_offsets[e + 1];
    int n0 = blockIdx.y * 128;

    int tid  = threadIdx.x;
    int wid  = tid >> 5, lane = tid & 31;
    int wm   = wid & 3;          // warp row  (4 x 32 rows)
    int wn   = wid >> 2;         // warp col  (2 x 64 cols)

    const __half* A  = (MODE == 1) ? g_x16 : g_h;
    const __half* Bw = ((MODE == 1) ? g_w1 : g_w2) + (size_t)e * KDIM * NTOT;

    uint32_t sbase = smem_u32(smem);

    // A copy mapping: rows tid>>2 and +64, k-seg tid&3 (16B each)
    int rowA0 = tid >> 2,  kc = tid & 3;
    int rowA1 = rowA0 + 64;
    int pA0 = r0 + rowA0; if (pA0 >= row_end) pA0 = r0;
    int pA1 = r0 + rowA1; if (pA1 >= row_end) pA1 = r0;
    // MODE 1: resolve permutation once (gather from unpermuted fp16 x)
    int srcA0 = (MODE == 1) ? g_perm[pA0] : pA0;
    int srcA1 = (MODE == 1) ? g_perm[pA1] : pA1;
    uint32_t offA0 = rowA0 * A_PITCH + kc * 16;
    uint32_t offA1 = rowA1 * A_PITCH + kc * 16;
    // B copy mapping: k-row tid>>3 (0..31), n-seg tid&7 and +8 (16B each)
    int brow = tid >> 3, bseg = tid & 7;
    uint32_t offB0 = brow * B_PITCH + bseg * 16;
    uint32_t offB1 = offB0 + 128;

    float acc[2][8][4];
#pragma unroll
    for (int i = 0; i < 2; i++)
#pragma unroll
        for (int j = 0; j < 8; j++)
#pragma unroll
            for (int q = 0; q < 4; q++) acc[i][j][q] = 0.f;

    auto issue = [&](int chunk, int slot) {
        int k0 = chunk * 32;
        uint32_t sA = sbase + slot * STAGE_B;
        uint32_t sB = sA + A_TILE;
        CP_ASYNC16(sA + offA0, A + (size_t)srcA0 * KDIM + k0 + kc * 8);
        CP_ASYNC16(sA + offA1, A + (size_t)srcA1 * KDIM + k0 + kc * 8);
        const __half* bsrc = Bw + (size_t)(k0 + brow) * NTOT + n0 + bseg * 8;
        CP_ASYNC16(sB + offB0, bsrc);
        CP_ASYNC16(sB + offB1, bsrc + 64);
    };

    issue(0, 0); CP_COMMIT();
    issue(1, 1); CP_COMMIT();
    issue(2, 2); CP_COMMIT();

    // lane address pieces
    int lrow = ((lane >> 3) & 1) * 8 + (lane & 7);        // A: m-row within 16
    int lkof = ((lane >> 4) & 1) * 8;                     // A: k-offset
    int bkrow = (lane & 7) + ((lane >> 4) & 1) * 8;       // B: k-row within 16
    int bncol = ((lane >> 3) & 1) * 8;                    // B: n-offset within 16

    for (int c = 0; c < NC; c++) {
        int slot = c & 3;
        if (c + 3 < NC) { CP_WAIT2(); }
        else            { CP_WAIT0(); }
        __syncthreads();
        if (c + 3 < NC) {
            issue(c + 3, (c + 3) & 3); CP_COMMIT();
        }

        uint32_t sA = sbase + slot * STAGE_B;
        uint32_t sB = sA + A_TILE;

#pragma unroll
        for (int kk = 0; kk < 2; kk++) {
            int k0 = kk * 16;
            // B fragments via trans ldmatrix on [k][n] tile:
            // reg0=(k0-7,n0-7) reg1=(k0-7,n8-15) reg2=(k8-15,n0-7) reg3=(k8-15,n8-15)
            uint32_t b[4][4];
#pragma unroll
            for (int g = 0; g < 4; g++) {
                uint32_t addr = sB + (uint32_t)((k0 + bkrow) * B_PITCH
                                                + (wn * 64 + g * 16 + bncol) * 2);
                LDSM4T(b[g][0], b[g][1], b[g][2], b[g][3], addr);
            }
            uint32_t a[2][4];
#pragma unroll
            for (int mi = 0; mi < 2; mi++) {
                uint32_t addr = sA + (uint32_t)((wm * 32 + mi * 16 + lrow) * A_PITCH
                                                + (k0 + lkof) * 2);
                LDSM4(a[mi][0], a[mi][1], a[mi][2], a[mi][3], addr);
            }
#pragma unroll
            for (int mi = 0; mi < 2; mi++)
#pragma unroll
                for (int ni = 0; ni < 8; ni++) {
                    int gg = ni >> 1, hh = ni & 1;
                    MMA16816(acc[mi][ni], a[mi], b[gg][hh], b[gg][hh + 2]);
                }
        }
    }

    // ---------------- epilogue ----------------
    int colbase = n0 + wn * 64 + (lane & 3) * 2;
    int rbase   = r0 + wm * 32 + (lane >> 2);
    size_t bofs = (size_t)e * NTOT;

#pragma unroll
    for (int mi = 0; mi < 2; mi++) {
#pragma unroll
        for (int half = 0; half < 2; half++) {
            int p = rbase + mi * 16 + half * 8;
            if (p >= row_end) continue;
            if (MODE == 1) {
#pragma unroll
                for (int ni = 0; ni < 8; ni++) {
                    int col = colbase + ni * 8;
                    float v0 = acc[mi][ni][half * 2]     + bias[bofs + col];
                    float v1 = acc[mi][ni][half * 2 + 1] + bias[bofs + col + 1];
                    v0 = gelu_exact(v0);
                    v1 = gelu_exact(v1);
                    uint32_t hw = ((uint32_t)__half_as_ushort(__float2half_rn(v1)) << 16)
                                  | __half_as_ushort(__float2half_rn(v0));
                    *(uint32_t*)(g_h + (size_t)p * H_ + col) = hw;
                }
            } else {
                int tok = g_perm[p];
                float gprob = g_prob[tok];
                float* orow = out + (size_t)tok * C_;
#pragma unroll
                for (int ni = 0; ni < 8; ni++) {
                    int col = colbase + ni * 8;
                    float2 o;
                    o.x = gprob * (acc[mi][ni][half * 2]     + bias[bofs + col]);
                    o.y = gprob * (acc[mi][ni][half * 2 + 1] + bias[bofs + col + 1]);
                    *(float2*)(orow + col) = o;
                }
            }
        }
    }
}

// ---------------- launch ------------------------------------------------------
extern "C" void kernel_launch(void* const* d_in, const int* in_sizes, int n_in,
                              void* d_out, int out_size) {
    const float* x  = (const float*)d_in[0];
    const float* Wr = (const float*)d_in[1];
    const float* br = (const float*)d_in[2];
    const float* W1 = (const float*)d_in[3];
    const float* b1 = (const float*)d_in[4];
    const float* W2 = (const float*)d_in[5];
    const float* b2 = (const float*)d_in[6];
    float* out = (float*)d_out;

    float* aux_ptr = (out_size > NTOK * C_) ? (out + (out_size - 1)) : nullptr;

    cudaFuncSetAttribute(gemm_hmma_kernel<1>,
                         cudaFuncAttributeMaxDynamicSharedMemorySize, GEMM_SMEM);
    cudaFuncSetAttribute(gemm_hmma_kernel<2>,
                         cudaFuncAttributeMaxDynamicSharedMemorySize, GEMM_SMEM);

    __half* d_w1h; cudaGetSymbolAddress((void**)&d_w1h, g_w1);
    __half* d_w2h; cudaGetSymbolAddress((void**)&d_w2h, g_w2);
    convert_w_kernel<<<(E_ * C_ * H_) / 8 / 256, 256>>>((const float4*)W1, d_w1h);
    convert_w_kernel<<<(E_ * H_ * C_) / 8 / 256, 256>>>((const float4*)W2, d_w2h);

    zero_counts_kernel<<<1, 32>>>();
    router_kernel<<<NTOK / 32, 256>>>(x, Wr, br);
    offsets_kernel<<<1, 1>>>(aux_ptr);
    permute_kernel<<<NTOK / 256, 256>>>();

    gemm_hmma_kernel<1><<<dim3(72, H_ / 128), 256, GEMM_SMEM>>>(b1, nullptr);
    gemm_hmma_kernel<2><<<dim3(72, C_ / 128), 256, GEMM_SMEM>>>(b2, out);
}

// round 14
// speedup vs baseline: 1.1193x; 1.0148x over previous
#include <cuda_runtime.h>
#include <cuda_fp16.h>
#include <math.h>
#include <stdint.h>

#define B_    4
#define T_    2048
#define C_    1024
#define E_    8
#define H_    4096
#define NTOK  (B_ * T_)     // 8192
#define MAXBLK 80           // >= sum ceil(count_e/128) worst case (64+8)

// ---------------- scratch (device globals; no runtime allocation) -----------
__device__ int   g_idx[NTOK];
__device__ float g_prob[NTOK];
__device__ int   g_counts[E_];
__device__ int   g_offsets[E_ + 1];
__device__ int   g_cursor[E_];
__device__ int   g_perm[NTOK];
__device__ int   g_nblk;
__device__ int   g_blk_e[MAXBLK];
__device__ int   g_blk_r0[MAXBLK];

// fp16 operands (single-rounded; fp32 accumulate in MMA). Weights keep native
// layout: W1 [e][C][H], W2 [e][H][C]  (both are [k][n] for their GEMM).
__device__ __half g_x16[(size_t)NTOK * C_];       // fp16 x, UNpermuted (router)
__device__ __half g_w1[(size_t)E_ * C_ * H_];     // fl16(W1)
__device__ __half g_w2[(size_t)E_ * H_ * C_];     // fl16(W2)
__device__ __half g_h[(size_t)NTOK * H_];         // hidden (permuted rows)

__device__ __forceinline__ float gelu_exact(float v) {
    return 0.5f * v * (1.0f + erff(v * 0.7071067811865476f));
}

__device__ __forceinline__ uint32_t smem_u32(const void* p) {
    uint32_t a;
    asm("{ .reg .u64 t; cvta.to.shared.u64 t, %1; cvt.u32.u64 %0, t; }"
        : "=r"(a) : "l"(p));
    return a;
}

#define LDSM4(R0, R1, R2, R3, addr)                                          \
    asm volatile("ldmatrix.sync.aligned.m8n8.x4.shared.b16 {%0,%1,%2,%3}, [%4];" \
                 : "=r"(R0), "=r"(R1), "=r"(R2), "=r"(R3) : "r"(addr))

#define LDSM4T(R0, R1, R2, R3, addr)                                         \
    asm volatile("ldmatrix.sync.aligned.m8n8.x4.trans.shared.b16 {%0,%1,%2,%3}, [%4];" \
                 : "=r"(R0), "=r"(R1), "=r"(R2), "=r"(R3) : "r"(addr))

#define MMA16816(C, A, B0, B1)                                               \
    asm volatile("mma.sync.aligned.m16n8k16.row.col.f32.f16.f16.f32 "        \
                 "{%0,%1,%2,%3},{%4,%5,%6,%7},{%8,%9},{%0,%1,%2,%3};"        \
                 : "+f"((C)[0]), "+f"((C)[1]), "+f"((C)[2]), "+f"((C)[3])    \
                 : "r"((A)[0]), "r"((A)[1]), "r"((A)[2]), "r"((A)[3]),       \
                   "r"(B0), "r"(B1))

#define CP_ASYNC16(dst, src)                                                 \
    asm volatile("cp.async.cg.shared.global [%0], [%1], 16;" :: "r"(dst), "l"(src))
#define CP_COMMIT()  asm volatile("cp.async.commit_group;" ::: "memory")
#define CP_WAIT2()   asm volatile("cp.async.wait_group 2;" ::: "memory")
#define CP_WAIT0()   asm volatile("cp.async.wait_group 0;" ::: "memory")

// ---------------- 0-3. routing -----------------------------------------------
__global__ void zero_counts_kernel() {
    if (threadIdx.x < E_) g_counts[threadIdx.x] = 0;
}

// 4 tokens per warp (Wr smem values reused x4); also emits fp16 x (unpermuted).
__global__ __launch_bounds__(256) void router_kernel(
        const float* __restrict__ x, const float* __restrict__ Wr,
        const float* __restrict__ br) {
    __shared__ float WrT[E_ * C_];          // 32 KB, [e][k]
    int tid = threadIdx.x;
    for (int idx = tid; idx < E_ * C_; idx += 256) {
        int k = idx >> 3, e = idx & 7;
        WrT[e * C_ + k] = Wr[idx];
    }
    __syncthreads();

    int lane = tid & 31;
    int t0 = (blockIdx.x * 8 + (tid >> 5)) * 4;     // 4 consecutive tokens/warp

    float acc[4][E_];
#pragma unroll
    for (int j = 0; j < 4; j++)
#pragma unroll
        for (int e = 0; e < E_; e++) acc[j][e] = 0.f;

#pragma unroll
    for (int i = 0; i < C_ / 128; i++) {
        int k = i * 128 + lane * 4;
        float4 xv[4];
#pragma unroll
        for (int j = 0; j < 4; j++) {
            xv[j] = *(const float4*)(x + (size_t)(t0 + j) * C_ + k);
            uint2 hw;
            hw.x = ((uint32_t)__half_as_ushort(__float2half_rn(xv[j].y)) << 16)
                   | __half_as_ushort(__float2half_rn(xv[j].x));
            hw.y = ((uint32_t)__half_as_ushort(__float2half_rn(xv[j].w)) << 16)
                   | __half_as_ushort(__float2half_rn(xv[j].z));
            *(uint2*)(g_x16 + (size_t)(t0 + j) * C_ + k) = hw;
        }
#pragma unroll
        for (int e = 0; e < E_; e++) {
            float4 w = *(const float4*)(WrT + e * C_ + k);
#pragma unroll
            for (int j = 0; j < 4; j++)
                acc[j][e] += xv[j].x * w.x + xv[j].y * w.y
                           + xv[j].z * w.z + xv[j].w * w.w;
        }
    }
#pragma unroll
    for (int j = 0; j < 4; j++) {
#pragma unroll
        for (int e = 0; e < E_; e++) {
#pragma unroll
            for (int off = 16; off > 0; off >>= 1)
                acc[j][e] += __shfl_xor_sync(0xffffffffu, acc[j][e], off);
        }
        if (lane == 0) {
            float lmax = -1e30f; int best = 0;
#pragma unroll
            for (int e = 0; e < E_; e++) {
                float l = acc[j][e] + br[e];
                acc[j][e] = l;
                if (l > lmax) { lmax = l; best = e; }
            }
            float s = 0.f;
#pragma unroll
            for (int e = 0; e < E_; e++) s += expf(acc[j][e] - lmax);
            g_prob[t0 + j] = 1.0f / s;
            g_idx[t0 + j]  = best;
            atomicAdd(&g_counts[best], 1);
        }
    }
}

__global__ void offsets_kernel(float* aux_out) {
    int off = 0;
    float aux = 0.f;
    int nb = 0;
#pragma unroll
    for (int e = 0; e < E_; e++) {
        g_offsets[e] = off;
        g_cursor[e]  = off;
        int c = g_counts[e];
        for (int r0 = off; r0 < off + c; r0 += 128) {
            g_blk_e[nb]  = e;
            g_blk_r0[nb] = r0;
            nb++;
        }
        off += c;
        float frac = (float)c / (float)NTOK;
        float d = frac - (1.0f / (float)E_);
        aux += d * d;
    }
    g_offsets[E_] = off;
    g_nblk = nb;
    if (aux_out) *aux_out = aux / (float)E_;
}

__global__ void permute_kernel() {
    int t = blockIdx.x * blockDim.x + threadIdx.x;
    if (t >= NTOK) return;
    int e = g_idx[t];
    int pos = atomicAdd(&g_cursor[e], 1);
    g_perm[pos] = t;
}

// ---------------- 5. weight convert fp32 -> fp16 (8 floats/thread) -----------
__global__ __launch_bounds__(256) void convert_w_kernel(
        const float4* __restrict__ src, __half* __restrict__ dst) {
    size_t i = ((size_t)blockIdx.x * 256 + threadIdx.x) * 2;
    float4 v0 = src[i];
    float4 v1 = src[i + 1];
    uint4 hw;
    hw.x = ((uint32_t)__half_as_ushort(__float2half_rn(v0.y)) << 16)
           | __half_as_ushort(__float2half_rn(v0.x));
    hw.y = ((uint32_t)__half_as_ushort(__float2half_rn(v0.w)) << 16)
           | __half_as_ushort(__float2half_rn(v0.z));
    hw.z = ((uint32_t)__half_as_ushort(__float2half_rn(v1.y)) << 16)
           | __half_as_ushort(__float2half_rn(v1.x));
    hw.w = ((uint32_t)__half_as_ushort(__float2half_rn(v1.w)) << 16)
           | __half_as_ushort(__float2half_rn(v1.z));
    *(uint4*)(dst + i * 4) = hw;
}

// ---------------- 6/7. HMMA grouped GEMM (fp16, native-layout B) --------------
// A tile [128 m][32 k] pitch 80B (non-trans LDSM). B tile [32 k][128 n] pitch
// 272B (trans LDSM, conflict-free). 4-stage cp.async pipeline.
// MODE 1 gathers A rows from unpermuted g_x16 via g_perm.
#define A_PITCH  80
#define A_TILE   10240            // 128*80
#define B_PITCH  272
#define B_TILE   8704             // 32*272
#define STAGE_B  (A_TILE + B_TILE)  // 18944
#define GEMM_SMEM (4 * STAGE_B)     // 75776

template<int MODE>
__global__ __launch_bounds__(256, 2) void gemm_hmma_kernel(
        const float* __restrict__ bias, float* __restrict__ out) {
    constexpr int KDIM = (MODE == 1) ? C_ : H_;
    constexpr int NTOT = (MODE == 1) ? H_ : C_;
    constexpr int NC   = KDIM / 32;        // chunks

    extern __shared__ char smem[];
    int bx = blockIdx.x;
    if (bx >= g_nblk) return;
    int e  = g_blk_e[bx];
    int r0 = g_blk_r0[bx];
    int row_end = g_offsets[e + 1];
    int n0 = blockIdx.y * 128;

    int tid  = threadIdx.x;
    int wid  = tid >> 5, lane = tid & 31;
    int wm   = wid & 3;          // warp row  (4 x 32 rows)
    int wn   = wid >> 2;         // warp col  (2 x 64 cols)

    const __half* A  = (MODE == 1) ? g_x16 : g_h;
    const __half* Bw = ((MODE == 1) ? g_w1 : g_w2) + (size_t)e * KDIM * NTOT;

    uint32_t sbase = smem_u32(smem);

    // A copy mapping: rows tid>>2 and +64, k-seg tid&3 (16B each)
    int rowA0 = tid >> 2,  kc = tid & 3;
    int rowA1 = rowA0 + 64;
    int pA0 = r0 + rowA0; if (pA0 >= row_end) pA0 = r0;
    int pA1 = r0 + rowA1; if (pA1 >= row_end) pA1 = r0;
    int srcA0 = (MODE == 1) ? g_perm[pA0] : pA0;
    int srcA1 = (MODE == 1) ? g_perm[pA1] : pA1;
    uint32_t offA0 = rowA0 * A_PITCH + kc * 16;
    uint32_t offA1 = rowA1 * A_PITCH + kc * 16;
    // B copy mapping: k-row tid>>3 (0..31), n-seg tid&7 and +8 (16B each)
    int brow = tid >> 3, bseg = tid & 7;
    uint32_t offB0 = brow * B_PITCH + bseg * 16;
    uint32_t offB1 = offB0 + 128;

    float acc[2][8][4];
#pragma unroll
    for (int i = 0; i < 2; i++)
#pragma unroll
        for (int j = 0; j < 8; j++)
#pragma unroll
            for (int q = 0; q < 4; q++) acc[i][j][q] = 0.f;

    auto issue = [&](int chunk, int slot) {
        int k0 = chunk * 32;
        uint32_t sA = sbase + slot * STAGE_B;
        uint32_t sB = sA + A_TILE;
        CP_ASYNC16(sA + offA0, A + (size_t)srcA0 * KDIM + k0 + kc * 8);
        CP_ASYNC16(sA + offA1, A + (size_t)srcA1 * KDIM + k0 + kc * 8);
        const __half* bsrc = Bw + (size_t)(k0 + brow) * NTOT + n0 + bseg * 8;
        CP_ASYNC16(sB + offB0, bsrc);
        CP_ASYNC16(sB + offB1, bsrc + 64);
    };

    issue(0, 0); CP_COMMIT();
    issue(1, 1); CP_COMMIT();
    issue(2, 2); CP_COMMIT();

    // lane address pieces
    int lrow = ((lane >> 3) & 1) * 8 + (lane & 7);        // A: m-row within 16
    int lkof = ((lane >> 4) & 1) * 8;                     // A: k-offset
    int bkrow = (lane & 7) + ((lane >> 4) & 1) * 8;       // B: k-row within 16
    int bncol = ((lane >> 3) & 1) * 8;                    // B: n-offset within 16

    for (int c = 0; c < NC; c++) {
        int slot = c & 3;
        if (c + 3 < NC) { CP_WAIT2(); }
        else            { CP_WAIT0(); }
        __syncthreads();
        if (c + 3 < NC) {
            issue(c + 3, (c + 3) & 3); CP_COMMIT();
        }

        uint32_t sA = sbase + slot * STAGE_B;
        uint32_t sB = sA + A_TILE;

#pragma unroll
        for (int kk = 0; kk < 2; kk++) {
            int k0 = kk * 16;
            // B fragments via trans ldmatrix on [k][n] tile:
            // reg0=(k0-7,n0-7) reg1=(k0-7,n8-15) reg2=(k8-15,n0-7) reg3=(k8-15,n8-15)
            uint32_t b[4][4];
#pragma unroll
            for (int g = 0; g < 4; g++) {
                uint32_t addr = sB + (uint32_t)((k0 + bkrow) * B_PITCH
                                                + (wn * 64 + g * 16 + bncol) * 2);
                LDSM4T(b[g][0], b[g][1], b[g][2], b[g][3], addr);
            }
            uint32_t a[2][4];
#pragma unroll
            for (int mi = 0; mi < 2; mi++) {
                uint32_t addr = sA + (uint32_t)((wm * 32 + mi * 16 + lrow) * A_PITCH
                                                + (k0 + lkof) * 2);
                LDSM4(a[mi][0], a[mi][1], a[mi][2], a[mi][3], addr);
            }
#pragma unroll
            for (int mi = 0; mi < 2; mi++)
#pragma unroll
                for (int ni = 0; ni < 8; ni++) {
                    int gg = ni >> 1, hh = ni & 1;
                    MMA16816(acc[mi][ni], a[mi], b[gg][hh], b[gg][hh + 2]);
                }
        }
    }

    // ---------------- epilogue ----------------
    int colbase = n0 + wn * 64 + (lane & 3) * 2;
    int rbase   = r0 + wm * 32 + (lane >> 2);
    size_t bofs = (size_t)e * NTOT;

#pragma unroll
    for (int mi = 0; mi < 2; mi++) {
#pragma unroll
        for (int half = 0; half < 2; half++) {
            int p = rbase + mi * 16 + half * 8;
            if (p >= row_end) continue;
            if (MODE == 1) {
#pragma unroll
                for (int ni = 0; ni < 8; ni++) {
                    int col = colbase + ni * 8;
                    float v0 = acc[mi][ni][half * 2]     + bias[bofs + col];
                    float v1 = acc[mi][ni][half * 2 + 1] + bias[bofs + col + 1];
                    v0 = gelu_exact(v0);
                    v1 = gelu_exact(v1);
                    uint32_t hw = ((uint32_t)__half_as_ushort(__float2half_rn(v1)) << 16)
                                  | __half_as_ushort(__float2half_rn(v0));
                    *(uint32_t*)(g_h + (size_t)p * H_ + col) = hw;
                }
            } else {
                int tok = g_perm[p];
                float gprob = g_prob[tok];
                float* orow = out + (size_t)tok * C_;
#pragma unroll
                for (int ni = 0; ni < 8; ni++) {
                    int col = colbase + ni * 8;
                    float2 o;
                    o.x = gprob * (acc[mi][ni][half * 2]     + bias[bofs + col]);
                    o.y = gprob * (acc[mi][ni][half * 2 + 1] + bias[bofs + col + 1]);
                    *(float2*)(orow + col) = o;
                }
            }
        }
    }
}

// ---------------- launch ------------------------------------------------------
extern "C" void kernel_launch(void* const* d_in, const int* in_sizes, int n_in,
                              void* d_out, int out_size) {
    const float* x  = (const float*)d_in[0];
    const float* Wr = (const float*)d_in[1];
    const float* br = (const float*)d_in[2];
    const float* W1 = (const float*)d_in[3];
    const float* b1 = (const float*)d_in[4];
    const float* W2 = (const float*)d_in[5];
    const float* b2 = (const float*)d_in[6];
    float* out = (float*)d_out;

    float* aux_ptr = (out_size > NTOK * C_) ? (out + (out_size - 1)) : nullptr;

    cudaFuncSetAttribute(gemm_hmma_kernel<1>,
                         cudaFuncAttributeMaxDynamicSharedMemorySize, GEMM_SMEM);
    cudaFuncSetAttribute(gemm_hmma_kernel<2>,
                         cudaFuncAttributeMaxDynamicSharedMemorySize, GEMM_SMEM);

    __half* d_w1h; cudaGetSymbolAddress((void**)&d_w1h, g_w1);
    __half* d_w2h; cudaGetSymbolAddress((void**)&d_w2h, g_w2);

    // Fork a side stream for weight conversion (graph-capture-safe branch):
    // w1 convert overlaps routing; w2 convert overlaps GEMM1.
    cudaStream_t s2;
    cudaStreamCreateWithFlags(&s2, cudaStreamNonBlocking);
    cudaEvent_t evFork, evW1, evW2;
    cudaEventCreateWithFlags(&evFork, cudaEventDisableTiming);
    cudaEventCreateWithFlags(&evW1, cudaEventDisableTiming);
    cudaEventCreateWithFlags(&evW2, cudaEventDisableTiming);

    cudaEventRecord(evFork, 0);
    cudaStreamWaitEvent(s2, evFork, 0);
    convert_w_kernel<<<(E_ * C_ * H_) / 8 / 256, 256, 0, s2>>>((const float4*)W1, d_w1h);
    cudaEventRecord(evW1, s2);
    convert_w_kernel<<<(E_ * H_ * C_) / 8 / 256, 256, 0, s2>>>((const float4*)W2, d_w2h);
    cudaEventRecord(evW2, s2);

    // main stream: routing chain
    zero_counts_kernel<<<1, 32>>>();
    router_kernel<<<NTOK / 32, 256>>>(x, Wr, br);
    offsets_kernel<<<1, 1>>>(aux_ptr);
    permute_kernel<<<NTOK / 256, 256>>>();

    cudaStreamWaitEvent(0, evW1, 0);
    gemm_hmma_kernel<1><<<dim3(72, H_ / 128), 256, GEMM_SMEM>>>(b1, nullptr);
    cudaStreamWaitEvent(0, evW2, 0);
    gemm_hmma_kernel<2><<<dim3(72, C_ / 128), 256, GEMM_SMEM>>>(b2, out);
}